// round 16
// baseline (speedup 1.0000x reference)
#include <cuda_runtime.h>
#include <cuda_fp16.h>
#include <cstdint>

#define BB 16
#define NN 16384
#define CC 128
#define KK 9
#define TM 128
#define THREADS 256
#define NCHUNK_CONV 72          // 8 c8 * 9 ko, K=16 each
#define NCHUNK 80               // + 8 skip chunks
#define NREGION 40              // 2 chunks per region
#define REGION_GB 8192          // bytes per W region in global
#define ROW_SB 80               // smem row stride (64B data + 16B pad)
#define BUF_B (128 * ROW_SB)    // 10240 per region buffer
#define NBUF 4

// smem layout (bytes)
#define WBUF_OFF 0                          // 4 * 10240 = 40960
#define PP_OFF   (NBUF * BUF_B)             // 40960, 8*8*9*80 = 46080
#define IDX_OFF  (PP_OFF + 46080)           // 87040, 128*9*4 = 4608
#define BIAS_OFF (IDX_OFF + 4608)           // 91648, 256*4
#define SMEM_TOTAL (BIAS_OFF + 1024 + 128)  // 92800

// W pre-permuted fp16: [region 40][o 128][k 32] (two perm16'd k16 halves)
__device__ __align__(16) __half g_W2[NREGION * 128 * 32];

// position p -> channel-within-16 (lane's 4 frag k-values = contiguous float4)
__host__ __device__ __forceinline__ int perm16(int p) {
    int e = p & 1;
    return (p < 8) ? ((p >> 1) * 4 + e) : (((p - 8) >> 1) * 4 + 2 + e);
}

__global__ void prep_w(const float* __restrict__ Wc, const float* __restrict__ Ws) {
    int t = blockIdx.x * blockDim.x + threadIdx.x;
    if (t < NREGION * 128 * 32) {
        int rg = t >> 12, rem = t & 4095, o = rem >> 5, kk = rem & 31;
        int ci = rg * 2 + (kk >> 4);
        int p  = kk & 15;
        float v;
        if (ci < NCHUNK_CONV) {
            int c8 = ci / 9, ko = ci % 9;
            v = Wc[o * 1152 + ko * CC + c8 * 16 + perm16(p)];
        } else {
            int cs = ci - NCHUNK_CONV;
            v = Ws[o * CC + cs * 16 + perm16(p)];
        }
        g_W2[t] = __float2half_rn(v);
    }
}

// ---------------- PTX helpers ----------------
__device__ __forceinline__ uint32_t smem_u32(const void* p) {
    uint32_t a;
    asm("{ .reg .u64 t; cvta.to.shared.u64 t, %1; cvt.u32.u64 %0, t; }" : "=r"(a) : "l"(p));
    return a;
}
#define CP_ASYNC16(dst, src) \
    asm volatile("cp.async.cg.shared.global [%0], [%1], 16;" :: "r"(dst), "l"(src))
#define CP_COMMIT() asm volatile("cp.async.commit_group;" ::: "memory")
#define CP_WAIT(n)  asm volatile("cp.async.wait_group %0;" :: "n"(n) : "memory")

__device__ __forceinline__ void ldsm_x4(uint32_t* r, uint32_t addr) {
    asm volatile("ldmatrix.sync.aligned.m8n8.x4.shared.b16 {%0,%1,%2,%3}, [%4];"
                 : "=r"(r[0]), "=r"(r[1]), "=r"(r[2]), "=r"(r[3]) : "r"(addr));
}
__device__ __forceinline__ void mma16816(float* c, const uint32_t* a,
                                         uint32_t b0, uint32_t b1) {
    asm volatile("mma.sync.aligned.m16n8k16.row.col.f32.f16.f16.f32 "
                 "{%0,%1,%2,%3}, {%4,%5,%6,%7}, {%8,%9}, {%0,%1,%2,%3};"
                 : "+f"(c[0]), "+f"(c[1]), "+f"(c[2]), "+f"(c[3])
                 : "r"(a[0]), "r"(a[1]), "r"(a[2]), "r"(a[3]), "r"(b0), "r"(b1));
}
__device__ __forceinline__ float elu(float v) {
    float e;
    asm("ex2.approx.f32 %0, %1;" : "=f"(e) : "f"(v * 1.44269504f));
    return v > 0.f ? v : e - 1.f;
}
// packed f32x2: d = a*b + d (lane-wise fp32 FMA)
#define FMA2(d, a, b) \
    asm("fma.rn.f32x2 %0, %1, %2, %0;" : "+l"(d) : "l"(a), "l"(b))
__device__ __forceinline__ uint64_t pk2(float lo, float hi) {
    uint64_t r;
    asm("mov.b64 %0, {%1, %2};" : "=l"(r) : "f"(lo), "f"(hi));
    return r;
}
__device__ __forceinline__ void unpk2(float& lo, float& hi, uint64_t v) {
    asm("mov.b64 {%0, %1}, %2;" : "=f"(lo), "=f"(hi) : "l"(v));
}
__device__ __forceinline__ uint32_t h2pack(float a, float b) {
    __half2 h = __floats2half2_rn(a, b);
    return *reinterpret_cast<uint32_t*>(&h);
}

// region fetch: 8KB, 256 threads x 2 x 16B, ONE commit
__device__ __forceinline__ void issue_region(uint32_t wbase, int rg, int tid) {
    const char* src = (const char*)g_W2 + (size_t)rg * REGION_GB;
    #pragma unroll
    for (int e = 0; e < 2; e++) {
        int id = tid + e * THREADS;            // 0..511
        int o = id >> 2, part = id & 3;        // 4 x 16B per 64B row
        uint32_t dst = wbase + (rg & (NBUF - 1)) * BUF_B + o * ROW_SB + part * 16;
        CP_ASYNC16(dst, src + o * 64 + part * 16);
    }
    CP_COMMIT();
}

__global__ __launch_bounds__(THREADS, 1)
void paiconv_p2(const float* __restrict__ x, const int* __restrict__ idxg,
                const float* __restrict__ P, const float* __restrict__ b_conv,
                const float* __restrict__ b_skip, float* __restrict__ out)
{
    extern __shared__ char smem[];
    const uint32_t sb = smem_u32(smem);
    const int tid  = threadIdx.x;
    const int lane = tid & 31;
    const int wid  = tid >> 5;
    const int n0   = blockIdx.x * TM;
    const int b    = blockIdx.y;

    int*   s_idx  = (int*)(smem + IDX_OFF);
    float* s_bias = (float*)(smem + BIAS_OFF);

    // start W pipeline: regions 0,1,2
    issue_region(sb + WBUF_OFF, 0, tid);
    issue_region(sb + WBUF_OFF, 1, tid);
    issue_region(sb + WBUF_OFF, 2, tid);

    // stage P pre-interleaved as pairs {P[row], P[row+8]}:
    //   layout [wid 8][s 8][ko 9] rows of 9 float2 (80B row)
    for (int t = tid; t < TM * 81; t += THREADS) {
        int node = t / 81;
        int rem = t - node * 81;
        int ko = rem / 9, j = rem - ko * 9;
        int w = node >> 4, sl = node & 15;
        int s = sl & 7, h = sl >> 3;
        *(float*)(smem + PP_OFF + w * 5760 + s * 720 + ko * 80 + j * 8 + h * 4)
            = P[(size_t)n0 * 81 + t];
    }
    for (int t = tid; t < TM * KK; t += THREADS) s_idx[t] = idxg[n0 * KK + t];
    if (tid < CC) { s_bias[tid] = b_conv[tid]; s_bias[CC + tid] = b_skip[tid]; }
    __syncthreads();

    const float* xb = x + (size_t)b * NN * CC;

    // lane-owned rows within warp m16 tile
    const int r0l = wid * 16 + (lane >> 2);      // local node 0..127
    const int r1l = r0l + 8;
    const int q4  = (lane & 3) * 16;             // byte offset of lane's float4

    int idxr[2][KK];
    #pragma unroll
    for (int j = 0; j < KK; j++) {
        idxr[0][j] = s_idx[r0l * KK + j];
        idxr[1][j] = s_idx[r1l * KK + j];
    }

    float acc[64];
    #pragma unroll
    for (int i = 0; i < 64; i++) acc[i] = 0.f;

    // packed gather cache: xp[j][c] = {x_row0[j].c, x_row1[j].c}
    uint64_t xp[KK][4];
    const uint32_t ldsm_base = sb + WBUF_OFF + (lane & 15) * ROW_SB + (lane >> 4) * 16;
    const char* ppbase = smem + PP_OFF + wid * 5760 + (lane >> 2) * 720;

    // ---------------- conv: 72 chunks (c8 outer, ko inner) ----------------
    int ci = 0;
    for (int c8 = 0; c8 < 8; c8++) {
        // gather channel-slice for 2 rows x 9 neighbors, packed (reused 9x)
        #pragma unroll
        for (int j = 0; j < KK; j++) {
            int ix0 = idxr[0][j], ix1 = idxr[1][j];
            float4 v0 = make_float4(0.f, 0.f, 0.f, 0.f);
            float4 v1 = v0;
            if ((unsigned)ix0 < (unsigned)NN)
                v0 = __ldg((const float4*)((const char*)xb + (size_t)ix0 * 512 + c8 * 64 + q4));
            if ((unsigned)ix1 < (unsigned)NN)
                v1 = __ldg((const float4*)((const char*)xb + (size_t)ix1 * 512 + c8 * 64 + q4));
            xp[j][0] = pk2(v0.x, v1.x);
            xp[j][1] = pk2(v0.y, v1.y);
            xp[j][2] = pk2(v0.z, v1.z);
            xp[j][3] = pk2(v0.w, v1.w);
        }
        #pragma unroll
        for (int ko = 0; ko < 9; ko++, ci++) {
            if ((ci & 1) == 0) {
                if (ci < 74) { CP_WAIT(2); } else if (ci == 74) { CP_WAIT(1); } else { CP_WAIT(0); }
                __syncthreads();
                int rg = (ci >> 1) + 3;
                if (rg < NREGION) issue_region(sb + WBUF_OFF, rg, tid);
            }

            // packed mix: vp[c] = sum_j pp[j] * xp[j][c]  (rows in lanes)
            const uint64_t* pp = (const uint64_t*)(ppbase + ko * 80);
            uint64_t vp0 = 0, vp1 = 0, vp2 = 0, vp3 = 0;
            #pragma unroll
            for (int j = 0; j < KK; j++) {
                uint64_t p = pp[j];
                FMA2(vp0, p, xp[j][0]);
                FMA2(vp1, p, xp[j][1]);
                FMA2(vp2, p, xp[j][2]);
                FMA2(vp3, p, xp[j][3]);
            }

            float r0c0, r1c0, r0c1, r1c1, r0c2, r1c2, r0c3, r1c3;
            unpk2(r0c0, r1c0, vp0);
            unpk2(r0c1, r1c1, vp1);
            unpk2(r0c2, r1c2, vp2);
            unpk2(r0c3, r1c3, vp3);

            uint32_t a[4];
            a[0] = h2pack(elu(r0c0), elu(r0c1));
            a[1] = h2pack(elu(r1c0), elu(r1c1));
            a[2] = h2pack(elu(r0c2), elu(r0c3));
            a[3] = h2pack(elu(r1c2), elu(r1c3));

            const uint32_t wb = ldsm_base + ((ci >> 1) & (NBUF - 1)) * BUF_B + (ci & 1) * 32;
            #pragma unroll
            for (int g = 0; g < 8; g++) {
                uint32_t bf[4];
                ldsm_x4(bf, wb + g * 16 * ROW_SB);
                mma16816(acc + (2 * g) * 4,     a, bf[0], bf[2]);
                mma16816(acc + (2 * g + 1) * 4, a, bf[1], bf[3]);
            }
        }
    }

    // ---------------- fold: acc = elu(acc + bc) + bs ----------------
    {
        const int cbase = (lane & 3) * 2;
        #pragma unroll
        for (int t = 0; t < 16; t++) {
            int col = t * 8 + cbase;
            float2 bc  = *(const float2*)(s_bias + col);
            float2 bs2 = *(const float2*)(s_bias + 128 + col);
            acc[t * 4 + 0] = elu(acc[t * 4 + 0] + bc.x) + bs2.x;
            acc[t * 4 + 1] = elu(acc[t * 4 + 1] + bc.y) + bs2.y;
            acc[t * 4 + 2] = elu(acc[t * 4 + 2] + bc.x) + bs2.x;
            acc[t * 4 + 3] = elu(acc[t * 4 + 3] + bc.y) + bs2.y;
        }
    }

    // ---------------- skip: 8 chunks, A = x directly ----------------
    for (int c8 = 0; c8 < 8; c8++, ci++) {
        if ((ci & 1) == 0) {
            if (ci < 74) { CP_WAIT(2); } else if (ci == 74) { CP_WAIT(1); } else { CP_WAIT(0); }
            __syncthreads();
            int rg = (ci >> 1) + 3;
            if (rg < NREGION) issue_region(sb + WBUF_OFF, rg, tid);
        }

        float4 v0 = __ldg((const float4*)((const char*)xb + (size_t)(n0 + r0l) * 512 + c8 * 64 + q4));
        float4 v1 = __ldg((const float4*)((const char*)xb + (size_t)(n0 + r1l) * 512 + c8 * 64 + q4));
        uint32_t a[4];
        a[0] = h2pack(v0.x, v0.y);
        a[1] = h2pack(v1.x, v1.y);
        a[2] = h2pack(v0.z, v0.w);
        a[3] = h2pack(v1.z, v1.w);

        const uint32_t wb = ldsm_base + ((ci >> 1) & (NBUF - 1)) * BUF_B + (ci & 1) * 32;
        #pragma unroll
        for (int g = 0; g < 8; g++) {
            uint32_t bf[4];
            ldsm_x4(bf, wb + g * 16 * ROW_SB);
            mma16816(acc + (2 * g) * 4,     a, bf[0], bf[2]);
            mma16816(acc + (2 * g + 1) * 4, a, bf[1], bf[3]);
        }
    }

    // ---------------- epilogue: store ----------------
    {
        const int cbase = (lane & 3) * 2;
        float* o0 = out + ((size_t)b * NN + n0 + r0l) * CC + cbase;
        float* o1 = out + ((size_t)b * NN + n0 + r1l) * CC + cbase;
        #pragma unroll
        for (int t = 0; t < 16; t++) {
            *(float2*)(o0 + t * 8) = make_float2(acc[t * 4 + 0], acc[t * 4 + 1]);
            *(float2*)(o1 + t * 8) = make_float2(acc[t * 4 + 2], acc[t * 4 + 3]);
        }
    }
}

extern "C" void kernel_launch(void* const* d_in, const int* in_sizes, int n_in,
                              void* d_out, int out_size) {
    const float* x       = (const float*)d_in[0];
    const int*   indices = (const int*)  d_in[1];
    const float* P       = (const float*)d_in[2];
    const float* W_conv  = (const float*)d_in[3];
    const float* b_conv  = (const float*)d_in[4];
    const float* W_skip  = (const float*)d_in[5];
    const float* b_skip  = (const float*)d_in[6];
    float* out = (float*)d_out;

    prep_w<<<(NREGION * 128 * 32 + 255) / 256, 256>>>(W_conv, W_skip);

    cudaFuncSetAttribute(paiconv_p2,
                         cudaFuncAttributeMaxDynamicSharedMemorySize, SMEM_TOTAL);
    dim3 grid(NN / TM, BB);
    paiconv_p2<<<grid, THREADS, SMEM_TOTAL>>>(x, indices, P, b_conv, b_skip, out);
}